// round 12
// baseline (speedup 1.0000x reference)
#include <cuda_runtime.h>

#define BATCH 32
#define IN_H  128
#define IN_W  512
#define CHAN  32
#define OUT_H 64
#define OUT_W 256

// Block = 256 threads, covers 128 points = 16 wx x 8 hy.
// Phase 1: threads 0..127 compute weights + pixel indices -> smem.
// Phase 2: 8 threads per point (float4 channel group), 4 points per thread.
// Stores via __stcg. 32 regs -> 8 CTAs/SM.
// Grid = 16 wx-tiles * 8 hy-tiles * 32 b = 4096 blocks.

struct PParam {
    float    wA, wB, wC, wD;
    unsigned iA, iB, iC, iD;   // pixel index * 8 (float4 units), without cg
};

__global__ void __launch_bounds__(256, 8)
stn_bilinear_kernel(const float* __restrict__ image,
                    const float* __restrict__ theta,
                    float* __restrict__ out)
{
    __shared__ PParam sp[128];

    const unsigned tid = threadIdx.x;
    const unsigned bid = blockIdx.x;
    const unsigned wx_base = (bid & 15u) << 4;       // 16 tiles of 16 wx
    const unsigned r       = bid >> 4;
    const unsigned hy_base = (r & 7u) << 3;          // 8 tiles of 8 hy
    const unsigned b       = r >> 3;                 // 0..31

    // ---- Phase 1: 128 threads compute params for the 16x8 point tile ----
    if (tid < 128u) {
        const unsigned wx = wx_base + (tid & 15u);
        const unsigned hy = hy_base + (tid >> 4);    // 8 consecutive rows

        const float xg = (float)wx * (2.0f / 255.0f) - 1.0f;
        const float yg = (float)hy * (2.0f / 63.0f) - 1.0f;

        // theta[b] 2x3; reference hack: zero row 1 of batch 0, row 0 of batch 1
        const float* th = theta + b * 6u;
        float t00 = __ldg(th + 0), t01 = __ldg(th + 1), t02 = __ldg(th + 2);
        float t10 = __ldg(th + 3), t11 = __ldg(th + 4), t12 = __ldg(th + 5);
        if (b == 0u) { t10 = 0.0f; t11 = 0.0f; t12 = 0.0f; }
        if (b == 1u) { t00 = 0.0f; t01 = 0.0f; t02 = 0.0f; }

        float cx = t00 * xg + t01 * yg + t02;
        float cy = t10 * xg + t11 * yg + t12;

        float x = 0.5f * (cx + 1.0f) * (float)IN_W;   // uses W, not W-1
        float y = 0.5f * (cy + 1.0f) * (float)IN_H;

        int x0 = (int)x;                              // trunc toward zero
        int y0 = (int)y;
        int x1 = x0 + 1;
        int y1 = y0 + 1;
        x0 = min(max(x0, 0), IN_W - 1);               // clip BEFORE weights
        x1 = min(max(x1, 0), IN_W - 1);
        y0 = min(max(y0, 0), IN_H - 1);
        y1 = min(max(y1, 0), IN_H - 1);

        float x0f = (float)x0, x1f = (float)x1;
        float y0f = (float)y0, y1f = (float)y1;

        PParam pp;
        pp.wA = (x1f - x) * (y1f - y);
        pp.wB = (x1f - x) * (y - y0f);
        pp.wC = (x - x0f) * (y1f - y);
        pp.wD = (x - x0f) * (y - y0f);

        const unsigned basePix = b * (unsigned)(IN_H * IN_W);
        const unsigned row0 = basePix + (unsigned)y0 * (unsigned)IN_W;
        const unsigned row1 = basePix + (unsigned)y1 * (unsigned)IN_W;
        pp.iA = (row0 + (unsigned)x0) << 3;
        pp.iB = (row1 + (unsigned)x0) << 3;
        pp.iC = (row0 + (unsigned)x1) << 3;
        pp.iD = (row1 + (unsigned)x1) << 3;

        sp[tid] = pp;
    }
    __syncthreads();

    // ---- Phase 2: 8 threads per point, 4 points per thread ----
    const unsigned cg = tid & 7u;
    const unsigned p0 = tid >> 3;        // 0..31 ; points p0 + 32k, k=0..3

    const float4* __restrict__ img4 = (const float4*)image;
    float4* __restrict__ out4 = (float4*)out;

    #pragma unroll
    for (int k = 0; k < 4; ++k) {
        const unsigned p  = p0 + (unsigned)k * 32u;
        const PParam pp = sp[p];

        float4 pA = __ldg(img4 + (pp.iA + cg));
        float4 pB = __ldg(img4 + (pp.iB + cg));
        float4 pC = __ldg(img4 + (pp.iC + cg));
        float4 pD = __ldg(img4 + (pp.iD + cg));

        float4 res;
        res.x = pA.x * pp.wA + pB.x * pp.wB + pC.x * pp.wC + pD.x * pp.wD;
        res.y = pA.y * pp.wA + pB.y * pp.wB + pC.y * pp.wC + pD.y * pp.wD;
        res.z = pA.z * pp.wA + pB.z * pp.wB + pC.z * pp.wC + pD.z * pp.wD;
        res.w = pA.w * pp.wA + pB.w * pp.wB + pC.w * pp.wC + pD.w * pp.wD;

        const unsigned wx = wx_base + (p & 15u);
        const unsigned hy = hy_base + (p >> 4);
        const unsigned oIdx = ((b * (unsigned)OUT_H + hy) * (unsigned)OUT_W + wx) * 8u + cg;
        __stcg(&out4[oIdx], res);
    }
}

extern "C" void kernel_launch(void* const* d_in, const int* in_sizes, int n_in,
                              void* d_out, int out_size)
{
    const float* image = (const float*)d_in[0];
    const float* theta = (const float*)d_in[1];
    float*       out   = (float*)d_out;

    stn_bilinear_kernel<<<4096, 256>>>(image, theta, out);
}

// round 14
// speedup vs baseline: 1.0204x; 1.0204x over previous
#include <cuda_runtime.h>

#define BATCH 32
#define IN_H  128
#define IN_W  512
#define CHAN  32
#define OUT_H 64
#define OUT_W 256

// R8 structure + software-pipelined gathers.
// Block = 256 threads, tile = 16 wx x 4 hy = 64 points.
// Phase 1: threads 0..63 compute weights + pixel indices -> smem.
// Phase 2: 8 threads per point, 2 points per thread; ALL 8 gathers issued
//          before any blend (payload 8 x float4 held live -> ~48 regs,
//          5 CTAs/SM), stores via __stcg.
// Grid = 16 wx-tiles * 16 hy-tiles * 32 b = 8192 blocks.

struct PParam {
    float    wA, wB, wC, wD;
    unsigned iA, iB, iC, iD;   // pixel index * 8 (float4 units), without cg
};

__global__ void __launch_bounds__(256, 5)
stn_bilinear_kernel(const float* __restrict__ image,
                    const float* __restrict__ theta,
                    float* __restrict__ out)
{
    __shared__ PParam sp[64];

    const unsigned tid = threadIdx.x;
    const unsigned bid = blockIdx.x;
    const unsigned wx_base = (bid & 15u) << 4;       // 16 tiles of 16 wx
    const unsigned r       = bid >> 4;
    const unsigned hy_base = (r & 15u) << 2;         // 16 tiles of 4 hy
    const unsigned b       = r >> 4;                 // 0..31

    // ---- Phase 1: 64 threads compute params for the 16x4 point tile ----
    if (tid < 64u) {
        const unsigned wx = wx_base + (tid & 15u);
        const unsigned hy = hy_base + (tid >> 4);

        const float xg = (float)wx * (2.0f / 255.0f) - 1.0f;
        const float yg = (float)hy * (2.0f / 63.0f) - 1.0f;

        // theta[b] 2x3; reference hack: zero row 1 of batch 0, row 0 of batch 1
        const float* th = theta + b * 6u;
        float t00 = __ldg(th + 0), t01 = __ldg(th + 1), t02 = __ldg(th + 2);
        float t10 = __ldg(th + 3), t11 = __ldg(th + 4), t12 = __ldg(th + 5);
        if (b == 0u) { t10 = 0.0f; t11 = 0.0f; t12 = 0.0f; }
        if (b == 1u) { t00 = 0.0f; t01 = 0.0f; t02 = 0.0f; }

        float cx = t00 * xg + t01 * yg + t02;
        float cy = t10 * xg + t11 * yg + t12;

        float x = 0.5f * (cx + 1.0f) * (float)IN_W;   // uses W, not W-1
        float y = 0.5f * (cy + 1.0f) * (float)IN_H;

        int x0 = (int)x;                              // trunc toward zero
        int y0 = (int)y;
        int x1 = x0 + 1;
        int y1 = y0 + 1;
        x0 = min(max(x0, 0), IN_W - 1);               // clip BEFORE weights
        x1 = min(max(x1, 0), IN_W - 1);
        y0 = min(max(y0, 0), IN_H - 1);
        y1 = min(max(y1, 0), IN_H - 1);

        float x0f = (float)x0, x1f = (float)x1;
        float y0f = (float)y0, y1f = (float)y1;

        PParam pp;
        pp.wA = (x1f - x) * (y1f - y);
        pp.wB = (x1f - x) * (y - y0f);
        pp.wC = (x - x0f) * (y1f - y);
        pp.wD = (x - x0f) * (y - y0f);

        const unsigned basePix = b * (unsigned)(IN_H * IN_W);
        const unsigned row0 = basePix + (unsigned)y0 * (unsigned)IN_W;
        const unsigned row1 = basePix + (unsigned)y1 * (unsigned)IN_W;
        pp.iA = (row0 + (unsigned)x0) << 3;
        pp.iB = (row1 + (unsigned)x0) << 3;
        pp.iC = (row0 + (unsigned)x1) << 3;
        pp.iD = (row1 + (unsigned)x1) << 3;

        sp[tid] = pp;
    }
    __syncthreads();

    // ---- Phase 2: 8 threads per point, 2 points per thread, pipelined ----
    const unsigned cg = tid & 7u;
    const unsigned p0 = tid >> 3;        // 0..31 ; second point = p0 + 32

    const float4* __restrict__ img4 = (const float4*)image;
    float4* __restrict__ out4 = (float4*)out;

    // Read both points' params up front (LDS broadcast)
    const PParam q0 = sp[p0];
    const PParam q1 = sp[p0 + 32u];

    // Issue ALL 8 gathers back-to-back
    float4 a0 = __ldg(img4 + (q0.iA + cg));
    float4 b0 = __ldg(img4 + (q0.iB + cg));
    float4 c0 = __ldg(img4 + (q0.iC + cg));
    float4 d0 = __ldg(img4 + (q0.iD + cg));
    float4 a1 = __ldg(img4 + (q1.iA + cg));
    float4 b1 = __ldg(img4 + (q1.iB + cg));
    float4 c1 = __ldg(img4 + (q1.iC + cg));
    float4 d1 = __ldg(img4 + (q1.iD + cg));

    const unsigned wx  = wx_base + (p0 & 15u);
    const unsigned hy0 = hy_base + (p0 >> 4);
    const unsigned oIdx0 = ((b * (unsigned)OUT_H + hy0) * (unsigned)OUT_W + wx) * 8u + cg;
    const unsigned oIdx1 = oIdx0 + 2u * (unsigned)OUT_W * 8u;   // hy0 + 2

    float4 r0;
    r0.x = a0.x * q0.wA + b0.x * q0.wB + c0.x * q0.wC + d0.x * q0.wD;
    r0.y = a0.y * q0.wA + b0.y * q0.wB + c0.y * q0.wC + d0.y * q0.wD;
    r0.z = a0.z * q0.wA + b0.z * q0.wB + c0.z * q0.wC + d0.z * q0.wD;
    r0.w = a0.w * q0.wA + b0.w * q0.wB + c0.w * q0.wC + d0.w * q0.wD;
    __stcg(&out4[oIdx0], r0);

    float4 r1;
    r1.x = a1.x * q1.wA + b1.x * q1.wB + c1.x * q1.wC + d1.x * q1.wD;
    r1.y = a1.y * q1.wA + b1.y * q1.wB + c1.y * q1.wC + d1.y * q1.wD;
    r1.z = a1.z * q1.wA + b1.z * q1.wB + c1.z * q1.wC + d1.z * q1.wD;
    r1.w = a1.w * q1.wA + b1.w * q1.wB + c1.w * q1.wC + d1.w * q1.wD;
    __stcg(&out4[oIdx1], r1);
}

extern "C" void kernel_launch(void* const* d_in, const int* in_sizes, int n_in,
                              void* d_out, int out_size)
{
    const float* image = (const float*)d_in[0];
    const float* theta = (const float*)d_in[1];
    float*       out   = (float*)d_out;

    stn_bilinear_kernel<<<8192, 256>>>(image, theta, out);
}